// round 15
// baseline (speedup 1.0000x reference)
#include <cuda_runtime.h>

// GHM-C loss, single-kernel: fused streaming pass + last-block finalize.
//
// Identity: weights are constant per histogram bin, so
//   pos_loss + neg_loss = sum_b w[b] * binsum[b],
//   binsum[b] = sum over in-bin elems of log(pred)*pos + log(1-pred)*(valid-pos)*(1-hm)^4.
// in_bin == valid for this data (g<1 whenever valid) -> tot = sum(counts).
// num_pos==0 branch redundant (pos_loss==0 there).
//
// Round-15 delta (base = round-13, 26.7us): WARP-AGGREGATED atomics.
//   mask = __match_any_sync(active, idx) groups same-bin lanes; REDUX.SUM
//   combines their fixed-point contributions q = (u32)fmaf(c, 2^22, 2^26);
//   the group leader issues ONE u64 atomicAdd of (qsum | popc(mask)<<48).
// -> atomic instructions 0.5 -> ~0.25/elem, ZERO intra-warp same-address
//    replay (groups hit distinct addresses), and the register count
//    machinery + shuffle tree are deleted (count rides in bits 48+).
// l1tex wavefronts were the binding resource (L1 48.6% best / 62% u64-flat /
// 86% disaster correlate exactly with runtime).
// Overflow: <=448 elems per (warp,bin) slot -> qsum <= 3e10 << 2^48; count < 2^16.
// Quantization 2^-22/elem: measured no rel_err change (round 14).
//
// |g| trick: for valid elems |g| = pos ? 1-p : p, logarg the opposite pick.
// Cache: pred __ldcg (partial L2 residency across replays), target __ldcs.
//
// Finalize: last block (ticket + threadfence), warp-parallel, resets globals
// so each graph replay starts clean (device globals zero-init at load).
//
// Shapes fixed: B=32, H=W=512 -> HW = 2^18.

static const int kHW  = 262144;
static const int kHW3 = 3 * 262144;

__device__ double       g_binsum[10];
__device__ int          g_counts[10];
__device__ unsigned int g_done;

__global__ void __launch_bounds__(256)
ghm_fused(const float* __restrict__ pred, const float* __restrict__ target,
          int nvec, float* __restrict__ out) {
    __shared__ unsigned long long s_bin[8][10];   // [warp][bin]: fx | cnt<<48
    __shared__ bool s_last;

    const float SCALE = 4194304.0f;    // 2^22
    const float BIAS  = 67108864.0f;   // 2^26

    int tid  = threadIdx.x;
    int wid  = tid >> 5;
    int lane = tid & 31;
    if (tid < 80) ((unsigned long long*)s_bin)[tid] = 0ull;
    __syncthreads();

    int stride = gridDim.x * blockDim.x;
    for (int v = blockIdx.x * blockDim.x + tid; v < nvec; v += stride) {
        int i = v << 2;
        int b = i / kHW;            // power of two -> shift
        int j = i - b * kHW;
        int tb = b * kHW3 + j;
        float4 p  = __ldcg((const float4*)(pred + i));           // L2-resident
        float4 hm = __ldcs((const float4*)(target + tb));        // streaming
        float4 va = __ldcs((const float4*)(target + tb + kHW));
        float4 po = __ldcs((const float4*)(target + tb + 2 * kHW));
        const float* pp = (const float*)&p;
        const float* hh = (const float*)&hm;
        const float* vv = (const float*)&va;
        const float* ss = (const float*)&po;
#pragma unroll
        for (int k = 0; k < 4; k++) {
            float pv = pp[k], hv = hh[k], v1 = vv[k], sv = ss[k];
            bool pin = v1 > 0.0f;      // in_bin == valid (g<1 when valid)
            bool isp = sv > 0.5f;      // pos (exact 0/1), pos => valid
            float omp  = 1.0f - pv;
            float ga   = isp ? omp : pv;   // |g| for valid elements
            float larg = isp ? pv : omp;   // log argument
            int idx = (int)(ga * 10.0f);
            idx = idx > 9 ? 9 : idx;

            // single-log loss term: pos ? log(p) : log(1-p)*(1-hm)^4
            float omh  = 1.0f - hv;
            float nw   = omh * omh; nw *= nw;
            float mult = isp ? 1.0f : nw;
            float c    = __logf(larg) * mult;
            unsigned q = (unsigned)fmaf(c, SCALE, BIAS);  // fixed-point, biased

            // warp-aggregate same-bin lanes; one atomic per group
            unsigned am  = __activemask();
            int key = pin ? idx : 16;                 // invalid lanes own group
            unsigned mask = __match_any_sync(am, key);
            if (pin) {
                unsigned qs = __reduce_add_sync(mask, q);
                if (lane == __ffs(mask) - 1) {
                    unsigned long long val = (unsigned long long)qs
                        | ((unsigned long long)__popc(mask) << 48);
                    atomicAdd(&s_bin[wid][idx], val);
                }
            }
        }
    }

    __syncthreads();
    if (tid < 10) {
        double fsum = 0.0;
        long long csum = 0;
#pragma unroll
        for (int w = 0; w < 8; w++) {
            unsigned long long vbin = s_bin[w][tid];
            unsigned long long cn = vbin >> 48;
            unsigned long long fx = vbin & 0x0000FFFFFFFFFFFFull;
            fsum += ((double)fx - (double)cn * 67108864.0) * (1.0 / 4194304.0);
            csum += (long long)cn;
        }
        atomicAdd(&g_binsum[tid], fsum);
        atomicAdd(&g_counts[tid], (int)csum);
    }
    __syncthreads();

    // ticket: last block to arrive finalizes
    if (tid == 0) {
        __threadfence();
        unsigned old = atomicAdd(&g_done, 1u);
        s_last = (old == (unsigned)gridDim.x - 1u);
    }
    __syncthreads();

    if (s_last && wid == 0) {
        __threadfence();   // all blocks' global atomics are visible
        int    c = (lane < 10) ? g_counts[lane] : 0;
        double bs = (lane < 10) ? g_binsum[lane] : 0.0;

        // warp reductions: tot, n_nonempty
        int toti = c, nn = (c > 0) ? 1 : 0;
#pragma unroll
        for (int o = 16; o > 0; o >>= 1) {
            toti += __shfl_down_sync(0xffffffffu, toti, o);
            nn   += __shfl_down_sync(0xffffffffu, nn, o);
        }
        toti = __shfl_sync(0xffffffffu, toti, 0);
        nn   = __shfl_sync(0xffffffffu, nn, 0);

        double tot = (double)(toti > 1 ? toti : 1);
        double nnf = (double)(nn > 1 ? nn : 1);
        double term = (c > 0) ? (tot / (double)c) / nnf * bs : 0.0;
#pragma unroll
        for (int o = 16; o > 0; o >>= 1)
            term += __shfl_down_sync(0xffffffffu, term, o);

        if (lane == 0) out[0] = (float)(-term / tot);
        // reset accumulators + ticket for the next graph replay
        if (lane < 10) { g_binsum[lane] = 0.0; g_counts[lane] = 0; }
        __threadfence();
        if (lane == 0) g_done = 0u;
    }
}

extern "C" void kernel_launch(void* const* d_in, const int* in_sizes, int n_in,
                              void* d_out, int out_size) {
    const float* pred   = (const float*)d_in[0];
    const float* target = (const float*)d_in[1];
    int npred = in_sizes[0];
    if (n_in >= 2 && in_sizes[1] < npred) {  // pred is the smaller tensor
        pred   = (const float*)d_in[1];
        target = (const float*)d_in[0];
        npred  = in_sizes[1];
    }
    int nvec = npred >> 2;

    ghm_fused<<<1184, 256>>>(pred, target, nvec, (float*)d_out);
}

// round 16
// speedup vs baseline: 2.4916x; 2.4916x over previous
#include <cuda_runtime.h>

// GHM-C loss, single-kernel: fused streaming pass + last-block finalize.
//
// Identity: weights are constant per histogram bin, so
//   pos_loss + neg_loss = sum_b w[b] * binsum[b],
//   binsum[b] = sum over in-bin elems of log(pred)*pos + log(1-pred)*(valid-pos)*(1-hm)^4.
// in_bin == valid for this data (g<1 whenever valid) -> tot = sum(counts).
// num_pos==0 branch redundant (pos_loss==0 there).
//
// This is the round-13 equilibrium build (26.7us: conditional f32 ATOMS into
// 4-way lane-split per-warp bins + u64 6-bit-field register counts) plus ONE
// subtractive change: |g| = pos ? 1-p : p for valid elements (g = p*valid-pos
// with pos,valid exact {0,1}), and the log argument is the opposite pick --
// replaces FFMA+FABS with selects off the already-needed 1-p.
// Restructurings tried and rejected by measurement: unconditional atomics
// (L1 86%, 82us), 8-wide ILP (regs 46, 37us), u64 packed atomics (L1 62%,
// 31us), warp-aggregated REDUX atomics (reconvergence stalls, 66us).
//
// Cache: pred __ldcg (partial L2 residency across graph replays), target
// __ldcs (evict-first stream).
//
// Finalize: last block (ticket + threadfence), warp-parallel, resets globals
// so each graph replay starts clean (device globals zero-init at load).
//
// Shapes fixed: B=32, H=W=512 -> HW = 2^18.

static const int kHW  = 262144;
static const int kHW3 = 3 * 262144;

__device__ double       g_binsum[10];
__device__ int          g_counts[10];
__device__ unsigned int g_done;

__global__ void __launch_bounds__(256)
ghm_fused(const float* __restrict__ pred, const float* __restrict__ target,
          int nvec, float* __restrict__ out) {
    __shared__ float s_bin[8][10][4];  // [warp][bin][lane&3 replica]
    __shared__ int   s_cnt[10];
    __shared__ bool  s_last;

    int tid = threadIdx.x;
    int wid = tid >> 5;
    int par = tid & 3;                  // 4-way replica
    for (int t = tid; t < 320; t += 256) ((float*)s_bin)[t] = 0.0f;
    if (tid < 10) s_cnt[tid] = 0;
    __syncthreads();

    // one u64 counter, 6-bit field per bin (max 28 per thread < 63)
    unsigned long long cnt = 0ull;

    int stride = gridDim.x * blockDim.x;
    for (int v = blockIdx.x * blockDim.x + tid; v < nvec; v += stride) {
        int i = v << 2;
        int b = i / kHW;            // power of two -> shift
        int j = i - b * kHW;
        int tb = b * kHW3 + j;
        float4 p  = __ldcg((const float4*)(pred + i));           // L2-resident
        float4 hm = __ldcs((const float4*)(target + tb));        // streaming
        float4 va = __ldcs((const float4*)(target + tb + kHW));
        float4 po = __ldcs((const float4*)(target + tb + 2 * kHW));
        const float* pp = (const float*)&p;
        const float* hh = (const float*)&hm;
        const float* vv = (const float*)&va;
        const float* ss = (const float*)&po;
#pragma unroll
        for (int k = 0; k < 4; k++) {
            float pv = pp[k], hv = hh[k], v1 = vv[k], sv = ss[k];
            bool pin = v1 > 0.0f;      // in_bin == valid (g<1 when valid)
            bool isp = sv > 0.5f;      // pos (exact 0/1), pos => valid
            float omp  = 1.0f - pv;
            float ga   = isp ? omp : pv;   // |g| for valid elements
            float larg = isp ? pv : omp;   // log argument
            int idx = (int)(ga * 10.0f);
            idx = idx > 9 ? 9 : idx;

            // single-log loss term: pos ? log(p) : log(1-p)*(1-hm)^4
            float omh  = 1.0f - hv;
            float nw   = omh * omh; nw *= nw;
            float mult = isp ? 1.0f : nw;
            float c    = __logf(larg) * mult;

            if (pin) atomicAdd(&s_bin[wid][idx][par], c);

            cnt += pin ? (1ull << (6 * idx)) : 0ull;
        }
    }

    // warp-reduce packed counts: split even/odd bins into 12-bit lanes
    // (field sums <= 28*32 = 896 < 4096, no overflow)
    unsigned long long evenF = cnt & 0x03F03F03F03F03Full;
    unsigned long long oddF  = (cnt >> 6) & 0x03F03F03F03F03Full;
#pragma unroll
    for (int o = 16; o > 0; o >>= 1) {
        evenF += __shfl_down_sync(0xffffffffu, evenF, o);
        oddF  += __shfl_down_sync(0xffffffffu, oddF, o);
    }
    if ((tid & 31) == 0) {
#pragma unroll
        for (int q = 0; q < 5; q++) {
            atomicAdd(&s_cnt[2 * q],     (int)((evenF >> (12 * q)) & 0xFFFull));
            atomicAdd(&s_cnt[2 * q + 1], (int)((oddF  >> (12 * q)) & 0xFFFull));
        }
    }
    __syncthreads();
    if (tid < 10) {
        float a = 0.0f;
#pragma unroll
        for (int w = 0; w < 8; w++)
#pragma unroll
            for (int r = 0; r < 4; r++) a += s_bin[w][tid][r];
        atomicAdd(&g_binsum[tid], (double)a);
        atomicAdd(&g_counts[tid], s_cnt[tid]);
    }
    __syncthreads();

    // ticket: last block to arrive finalizes
    if (tid == 0) {
        __threadfence();
        unsigned old = atomicAdd(&g_done, 1u);
        s_last = (old == (unsigned)gridDim.x - 1u);
    }
    __syncthreads();

    if (s_last && wid == 0) {
        __threadfence();   // all blocks' global atomics are visible
        int lane = tid;    // warp 0: lanes 0..31
        int    c = (lane < 10) ? g_counts[lane] : 0;
        double bs = (lane < 10) ? g_binsum[lane] : 0.0;

        // warp reductions: tot, n_nonempty
        int toti = c, nn = (c > 0) ? 1 : 0;
#pragma unroll
        for (int o = 16; o > 0; o >>= 1) {
            toti += __shfl_down_sync(0xffffffffu, toti, o);
            nn   += __shfl_down_sync(0xffffffffu, nn, o);
        }
        toti = __shfl_sync(0xffffffffu, toti, 0);
        nn   = __shfl_sync(0xffffffffu, nn, 0);

        double tot = (double)(toti > 1 ? toti : 1);
        double nnf = (double)(nn > 1 ? nn : 1);
        double term = (c > 0) ? (tot / (double)c) / nnf * bs : 0.0;
#pragma unroll
        for (int o = 16; o > 0; o >>= 1)
            term += __shfl_down_sync(0xffffffffu, term, o);

        if (lane == 0) out[0] = (float)(-term / tot);
        // reset accumulators + ticket for the next graph replay
        if (lane < 10) { g_binsum[lane] = 0.0; g_counts[lane] = 0; }
        __threadfence();
        if (lane == 0) g_done = 0u;
    }
}

extern "C" void kernel_launch(void* const* d_in, const int* in_sizes, int n_in,
                              void* d_out, int out_size) {
    const float* pred   = (const float*)d_in[0];
    const float* target = (const float*)d_in[1];
    int npred = in_sizes[0];
    if (n_in >= 2 && in_sizes[1] < npred) {  // pred is the smaller tensor
        pred   = (const float*)d_in[1];
        target = (const float*)d_in[0];
        npred  = in_sizes[1];
    }
    int nvec = npred >> 2;

    ghm_fused<<<1184, 256>>>(pred, target, nvec, (float*)d_out);
}